// round 3
// baseline (speedup 1.0000x reference)
#include <cuda_runtime.h>
#include <cstdint>

// LSTM: B=2048, T=1024, I=8, H=64. out = sigmoid(h_T @ fc_w^T + fc_b), [B,1] fp32.
//
// Strategy: one block = 8 batch rows, persistent over all 1024 timesteps.
// Recurrent matvec uses packed fp32 FMA (fma.rn.f32x2) with weights held in
// registers (constant across steps). K = 72 = 64 (h) + 8 (x_t), split in two
// halves across thread groups; partial sums reduced through shared memory.
// h is stored duplicated ({h,h} in a u64) so a single uniform (broadcast)
// ld.shared.v2.u64 feeds two FFMA2.

#define T_STEPS 1024
#define BB 8          // batch rows per block
#define KDIM 72       // 64 h + 8 x
#define KH 36         // K per half

__device__ __forceinline__ unsigned long long pk2(float lo, float hi) {
    unsigned long long r;
    asm("mov.b64 %0, {%1, %2};" : "=l"(r) : "f"(lo), "f"(hi));
    return r;
}
__device__ __forceinline__ void upk2(unsigned long long v, float& lo, float& hi) {
    asm("mov.b64 {%0, %1}, %2;" : "=f"(lo), "=f"(hi) : "l"(v));
}
__device__ __forceinline__ float ex2a(float x) {
    float r; asm("ex2.approx.f32 %0, %1;" : "=f"(r) : "f"(x)); return r;
}
__device__ __forceinline__ float rcpa(float x) {
    float r; asm("rcp.approx.f32 %0, %1;" : "=f"(r) : "f"(x)); return r;
}
// sigmoid(x) = 1 / (1 + 2^(-x*log2e))
__device__ __forceinline__ float sigm(float x) {
    return rcpa(1.0f + ex2a(-1.4426950408889634f * x));
}
// tanh(x) = 1 - 2 / (1 + 2^(2x*log2e))
__device__ __forceinline__ float tanha(float x) {
    return fmaf(-2.0f, rcpa(1.0f + ex2a(2.8853900817779268f * x)), 1.0f);
}

__global__ void __launch_bounds__(256, 2)
lstm_kernel(const float* __restrict__ x,     // [2048,1024,8]
            const float* __restrict__ Wih,   // [256,8]
            const float* __restrict__ Whh,   // [256,64]
            const float* __restrict__ bih,   // [256]
            const float* __restrict__ bhh,   // [256]
            const float* __restrict__ fcw,   // [64]
            const float* __restrict__ fcb,   // [1]
            float* __restrict__ out)         // [2048]
{
    // s_h[r][k] = {v,v} duplicated; k<64: h units, k>=64: x_t inputs
    __shared__ __align__(16) unsigned long long s_h[BB][KDIM];
    __shared__ unsigned long long s_part[BB][128];   // half-1 partial sums
    __shared__ float s_g[BB][256];                   // activated gates

    const int tid  = threadIdx.x;
    const int p    = tid & 127;   // output pair index: outputs 2p, 2p+1
    const int half = tid >> 7;    // k-half: 0 -> k in [0,36), 1 -> k in [36,72)
    const int j0   = 2 * p;

    // ---- persistent weight registers: w[kk] = {W[j0][k], W[j0+1][k]} ----
    unsigned long long w[KH];
#pragma unroll
    for (int kk = 0; kk < KH; ++kk) {
        int k = half * KH + kk;
        float lo, hi;
        if (k < 64) { lo = Whh[j0 * 64 + k];        hi = Whh[(j0 + 1) * 64 + k]; }
        else        { lo = Wih[j0 * 8 + (k - 64)];  hi = Wih[(j0 + 1) * 8 + (k - 64)]; }
        w[kk] = pk2(lo, hi);
    }
    unsigned long long bias2 = 0ULL;
    if (half == 0)
        bias2 = pk2(bih[j0] + bhh[j0], bih[j0 + 1] + bhh[j0 + 1]);

    // ---- cell-state owner mapping: thread owns unit u of rows r0 and r0+4 ----
    const int u  = tid & 63;
    const int r0 = tid >> 6;          // 0..3
    float c0 = 0.0f, c1 = 0.0f;

    // ---- x stager mapping (threads 0..63): row sr, input sxi ----
    const int sr  = (tid < 64) ? (tid >> 3) : 0;
    const int sxi = tid & 7;
    const float* xrow = x + (size_t)(blockIdx.x * BB + sr) * (T_STEPS * 8) + sxi;

    const uint32_t hb = (uint32_t)__cvta_generic_to_shared(&s_h[0][0]);
    const uint32_t pb = (uint32_t)__cvta_generic_to_shared(&s_part[0][0]);
    const uint32_t hB = hb + (uint32_t)(half * (KH * 8));  // this half's k-base

    // ---- init: h = 0, stage x(t=0) ----
    for (int i = tid; i < BB * 64; i += 256)
        s_h[i >> 6][i & 63] = 0ULL;
    if (tid < 64) {
        float xv = xrow[0];
        s_h[sr][64 + sxi] = pk2(xv, xv);
    }
    __syncthreads();

    for (int t = 0; t < T_STEPS; ++t) {
        // prefetch next timestep's x (consumed far below -> latency hidden)
        const bool pre = (t < T_STEPS - 1) && (tid < 64);
        float xn = 0.0f;
        if (pre) xn = __ldg(xrow + (t + 1) * 8);

        // ---- phase B: packed partial dot products over this thread's K half ----
        unsigned long long acc[BB];
#pragma unroll
        for (int r = 0; r < BB; ++r) {
            unsigned long long a = (half == 0) ? bias2 : 0ULL;
            uint32_t ad = hB + (uint32_t)(r * (KDIM * 8));
#pragma unroll
            for (int q = 0; q < KH / 2; ++q) {
                unsigned long long h0, h1;
                asm("ld.shared.v2.u64 {%0, %1}, [%2];"
                    : "=l"(h0), "=l"(h1) : "r"(ad + q * 16));
                asm("fma.rn.f32x2 %0, %1, %2, %0;" : "+l"(a) : "l"(w[2 * q]),     "l"(h0));
                asm("fma.rn.f32x2 %0, %1, %2, %0;" : "+l"(a) : "l"(w[2 * q + 1]), "l"(h1));
            }
            acc[r] = a;
        }

        // ---- phase C: half-1 publishes partials ----
        if (half == 1) {
#pragma unroll
            for (int r = 0; r < BB; ++r)
                asm volatile("st.shared.u64 [%0], %1;"
                             :: "r"(pb + (uint32_t)((r * 128 + p) * 8)), "l"(acc[r])
                             : "memory");
        }
        __syncthreads();

        // ---- phase D: half-0 reduces, activates, writes gates ----
        if (half == 0) {
            const bool is_tanh_gate = ((p >> 5) == 2);   // gate order i,f,g,o
#pragma unroll
            for (int r = 0; r < BB; ++r) {
                unsigned long long part, s;
                asm("ld.shared.u64 %0, [%1];"
                    : "=l"(part) : "r"(pb + (uint32_t)((r * 128 + p) * 8)));
                asm("add.rn.f32x2 %0, %1, %2;" : "=l"(s) : "l"(acc[r]), "l"(part));
                float glo, ghi;
                upk2(s, glo, ghi);
                float alo, ahi;
                if (is_tanh_gate) { alo = tanha(glo); ahi = tanha(ghi); }
                else              { alo = sigm(glo);  ahi = sigm(ghi);  }
                uint32_t ga = (uint32_t)__cvta_generic_to_shared(&s_g[r][2 * p]);
                asm volatile("st.shared.v2.f32 [%0], {%1, %2};"
                             :: "r"(ga), "f"(alo), "f"(ahi) : "memory");
            }
        }
        __syncthreads();

        // ---- phase E: owners update c, h; stagers write x(t+1) ----
        {
            float iv = s_g[r0][u], fv = s_g[r0][64 + u];
            float gv = s_g[r0][128 + u], ov = s_g[r0][192 + u];
            c0 = fmaf(fv, c0, iv * gv);
            float hv = ov * tanha(c0);
            s_h[r0][u] = pk2(hv, hv);

            const int r1 = r0 + 4;
            float iv1 = s_g[r1][u], fv1 = s_g[r1][64 + u];
            float gv1 = s_g[r1][128 + u], ov1 = s_g[r1][192 + u];
            c1 = fmaf(fv1, c1, iv1 * gv1);
            float hv1 = ov1 * tanha(c1);
            s_h[r1][u] = pk2(hv1, hv1);
        }
        if (pre) s_h[sr][64 + sxi] = pk2(xn, xn);
        __syncthreads();
    }

    // ---- head: out[row] = sigmoid(h_T . fc_w + fc_b) ----
    if (tid < BB) {
        const float* hp = (const float*)&s_h[tid][0];  // duplicated pairs; lane .x = h
        float acco = fcb[0];
#pragma unroll 8
        for (int uu = 0; uu < 64; ++uu)
            acco = fmaf(hp[2 * uu], fcw[uu], acco);
        out[blockIdx.x * BB + tid] = sigm(acco);
    }
}

extern "C" void kernel_launch(void* const* d_in, const int* in_sizes, int n_in,
                              void* d_out, int out_size)
{
    const float* x   = (const float*)d_in[0];
    const float* Wih = (const float*)d_in[1];
    const float* Whh = (const float*)d_in[2];
    const float* bih = (const float*)d_in[3];
    const float* bhh = (const float*)d_in[4];
    const float* fcw = (const float*)d_in[5];
    const float* fcb = (const float*)d_in[6];
    lstm_kernel<<<2048 / BB, 256>>>(x, Wih, Whh, bih, bhh, fcw, fcb, (float*)d_out);
}

// round 4
// speedup vs baseline: 1.4266x; 1.4266x over previous
#include <cuda_runtime.h>
#include <cstdint>

// LSTM: B=2048, T=1024, I=8, H=64. out = sigmoid(h_T @ fc_w^T + fc_b), [B,1] fp32.
//
// R4: k-pair packed fp32x2 FMA (1 LDS.128 feeds 4 FFMA2), grid 296 = 2 blocks
// on every SM, symmetric half-split reduction. Weights persist in registers.
// K = 72 = 64 (h) + 8 (x_t) folded into one recurrence; K split in halves of 36
// across the two thread-halves; partials exchanged through shared memory.

#define TT   1024
#define RMAX 7

typedef unsigned long long u64;

__device__ __forceinline__ u64 pk2(float lo, float hi) {
    u64 r; asm("mov.b64 %0, {%1, %2};" : "=l"(r) : "f"(lo), "f"(hi)); return r;
}
__device__ __forceinline__ void upk2(u64 v, float& lo, float& hi) {
    asm("mov.b64 {%0, %1}, %2;" : "=f"(lo), "=f"(hi) : "l"(v));
}
__device__ __forceinline__ float ex2a(float x) {
    float r; asm("ex2.approx.f32 %0, %1;" : "=f"(r) : "f"(x)); return r;
}
__device__ __forceinline__ float rcpa(float x) {
    float r; asm("rcp.approx.f32 %0, %1;" : "=f"(r) : "f"(x)); return r;
}
__device__ __forceinline__ float sigm(float x) {
    return rcpa(1.0f + ex2a(-1.4426950408889634f * x));
}
__device__ __forceinline__ float tanha(float x) {
    return fmaf(-2.0f, rcpa(1.0f + ex2a(2.8853900817779268f * x)), 1.0f);
}

// dot of one row's K-half into packed accumulators A0 (output j0), A1 (output j0+1)
#define ROWDOT(R, A0, A1) do {                                                   \
    u64 _h01, _h23; uint32_t _ad = hB + (R) * 288;                               \
    A0 = bias0; A1 = bias1;                                                      \
    _Pragma("unroll")                                                            \
    for (int q = 0; q < 9; ++q) {                                                \
        asm("ld.shared.v2.u64 {%0, %1}, [%2];"                                   \
            : "=l"(_h01), "=l"(_h23) : "r"(_ad + q * 16));                       \
        asm("fma.rn.f32x2 %0, %1, %2, %0;" : "+l"(A0) : "l"(w0[2*q]),   "l"(_h01)); \
        asm("fma.rn.f32x2 %0, %1, %2, %0;" : "+l"(A1) : "l"(w1[2*q]),   "l"(_h01)); \
        asm("fma.rn.f32x2 %0, %1, %2, %0;" : "+l"(A0) : "l"(w0[2*q+1]), "l"(_h23)); \
        asm("fma.rn.f32x2 %0, %1, %2, %0;" : "+l"(A1) : "l"(w1[2*q+1]), "l"(_h23)); \
    }                                                                            \
} while (0)

#define STPART(R, A0, A1)                                                        \
    asm volatile("st.shared.v2.u64 [%0], {%1, %2};"                              \
                 :: "r"(pB + (R) * 2048 + p * 16), "l"(A0), "l"(A1) : "memory")

// combine own packed acc with partner's partial, fold even+odd, activate, store gates
#define REDUCE(R, A0, A1) do {                                                   \
    u64 _p0, _p1, _s0, _s1;                                                      \
    asm("ld.shared.v2.u64 {%0, %1}, [%2];"                                       \
        : "=l"(_p0), "=l"(_p1) : "r"(pB + (R) * 2048 + p * 16));                 \
    asm("add.rn.f32x2 %0, %1, %2;" : "=l"(_s0) : "l"(A0), "l"(_p0));             \
    asm("add.rn.f32x2 %0, %1, %2;" : "=l"(_s1) : "l"(A1), "l"(_p1));             \
    float _e0, _o0, _e1, _o1; upk2(_s0, _e0, _o0); upk2(_s1, _e1, _o1);          \
    float _f0 = _e0 + _o0, _f1 = _e1 + _o1, _a0, _a1;                            \
    if (istanh) { _a0 = tanha(_f0); _a1 = tanha(_f1); }                          \
    else        { _a0 = sigm(_f0);  _a1 = sigm(_f1);  }                          \
    asm volatile("st.shared.v2.f32 [%0], {%1, %2};"                              \
                 :: "r"(gB + (R) * 1024 + p * 8), "f"(_a0), "f"(_a1) : "memory");\
} while (0)

__global__ void __launch_bounds__(256, 2)
lstm_kernel(const float* __restrict__ x,     // [2048,1024,8]
            const float* __restrict__ Wih,   // [256,8]
            const float* __restrict__ Whh,   // [256,64]
            const float* __restrict__ bih,   // [256]
            const float* __restrict__ bhh,   // [256]
            const float* __restrict__ fcw,   // [64]
            const float* __restrict__ fcb,   // [1]
            float* __restrict__ out)         // [2048]
{
    __shared__ __align__(16) float s_h[RMAX][72];        // [row][k]: k<64 h, k>=64 x
    __shared__ __align__(16) u64   s_part[RMAX][128][2]; // partner partials
    __shared__ __align__(16) float s_g[RMAX][256];       // activated gates

    const int tid  = threadIdx.x;
    const int p    = tid & 127;   // output pair: outputs 2p, 2p+1
    const int half = tid >> 7;    // K-half: k in [half*36, half*36+36)
    const int bid  = blockIdx.x;
    const int nrows   = (bid < 272) ? 7 : 6;
    const int rowbase = (bid < 272) ? bid * 7 : 1904 + (bid - 272) * 6;

    const int j0 = 2 * p;
    const int kb = half * 36;

    // ---- persistent weights: k-pair packed per output ----
    u64 w0[18], w1[18];
#pragma unroll
    for (int q = 0; q < 18; ++q) {
        int k = kb + 2 * q;
        float a = (k     < 64) ? Whh[j0 * 64 + k]           : Wih[j0 * 8 + (k - 64)];
        float b = (k + 1 < 64) ? Whh[j0 * 64 + k + 1]       : Wih[j0 * 8 + (k + 1 - 64)];
        float c = (k     < 64) ? Whh[(j0 + 1) * 64 + k]     : Wih[(j0 + 1) * 8 + (k - 64)];
        float d = (k + 1 < 64) ? Whh[(j0 + 1) * 64 + k + 1] : Wih[(j0 + 1) * 8 + (k + 1 - 64)];
        w0[q] = pk2(a, b);
        w1[q] = pk2(c, d);
    }
    u64 bias0 = 0ULL, bias1 = 0ULL;
    if (half == 0) {   // bias injected exactly once per (row, output), in even lane
        bias0 = pk2(bih[j0] + bhh[j0], 0.0f);
        bias1 = pk2(bih[j0 + 1] + bhh[j0 + 1], 0.0f);
    }

    const uint32_t hB = (uint32_t)__cvta_generic_to_shared(&s_h[0][0]) + kb * 4;
    const uint32_t pB = (uint32_t)__cvta_generic_to_shared(&s_part[0][0][0]);
    const uint32_t gB = (uint32_t)__cvta_generic_to_shared(&s_g[0][0]);

    // ---- cell owners: thread -> (unit u, rows r0 and r0+4) ----
    const int u  = tid & 63;
    const int r0 = tid >> 6;                         // 0..3
    const bool hasR1 = (r0 < 3) && (r0 + 4 < nrows);
    float c0 = 0.0f, c1 = 0.0f;

    // ---- x stagers: threads 0..55 -> (row sr, input sxi) ----
    const int  sr  = (tid >> 3) & 7;
    const int  sxi = tid & 7;
    const bool isStager = (tid < 56) && (sr < nrows);
    const float* xrow = x + (size_t)(rowbase + sr) * (TT * 8) + sxi;

    // ---- init: zero h/x, stage x(t=0) ----
    for (int i = tid; i < RMAX * 72; i += 256)
        (&s_h[0][0])[i] = 0.0f;
    __syncthreads();
    if (isStager) s_h[sr][64 + sxi] = __ldg(xrow);
    __syncthreads();

    const bool istanh = ((p >> 5) == 2);   // gate order i,f,g,o -> outputs 128..191 tanh

    u64 A0a, A0b, A1a, A1b, A2a, A2b, A3a, A3b;   // kept-row accumulators

#pragma unroll 1
    for (int t = 0; t < TT; ++t) {
        float xn = 0.0f;
        const bool pre = isStager && (t + 1 < TT);
        if (pre) xn = __ldg(xrow + (t + 1) * 8);

        // ---- phase B: partner rows first (store partials), own rows kept in regs ----
        if (half == 0) {
            { u64 B0, B1;
              ROWDOT(4, B0, B1); STPART(4, B0, B1);
              ROWDOT(5, B0, B1); STPART(5, B0, B1);
              ROWDOT(6, B0, B1); STPART(6, B0, B1); }
            ROWDOT(0, A0a, A0b);
            ROWDOT(1, A1a, A1b);
            ROWDOT(2, A2a, A2b);
            ROWDOT(3, A3a, A3b);
        } else {
            { u64 B0, B1;
              ROWDOT(0, B0, B1); STPART(0, B0, B1);
              ROWDOT(1, B0, B1); STPART(1, B0, B1);
              ROWDOT(2, B0, B1); STPART(2, B0, B1);
              ROWDOT(3, B0, B1); STPART(3, B0, B1); }
            ROWDOT(4, A0a, A0b);
            ROWDOT(5, A1a, A1b);
            ROWDOT(6, A2a, A2b);
        }
        __syncthreads();

        // ---- phase D: each half reduces + activates its own rows ----
        if (half == 0) {
            REDUCE(0, A0a, A0b); REDUCE(1, A1a, A1b);
            REDUCE(2, A2a, A2b); REDUCE(3, A3a, A3b);
        } else {
            REDUCE(4, A0a, A0b); REDUCE(5, A1a, A1b); REDUCE(6, A2a, A2b);
        }
        __syncthreads();

        // ---- phase E: cell/hidden update + x(t+1) staging ----
        {
            float iv = s_g[r0][u],       fv = s_g[r0][64 + u];
            float gv = s_g[r0][128 + u], ov = s_g[r0][192 + u];
            c0 = fmaf(fv, c0, iv * gv);
            s_h[r0][u] = ov * tanha(c0);
            if (hasR1) {
                const int r1 = r0 + 4;
                float iv1 = s_g[r1][u],       fv1 = s_g[r1][64 + u];
                float gv1 = s_g[r1][128 + u], ov1 = s_g[r1][192 + u];
                c1 = fmaf(fv1, c1, iv1 * gv1);
                s_h[r1][u] = ov1 * tanha(c1);
            }
            if (pre) s_h[sr][64 + sxi] = xn;
        }
        __syncthreads();
    }

    // ---- head: out[row] = sigmoid(h_T . fc_w + fc_b) ----
    if (tid < nrows) {
        const float* hp = s_h[tid];
        float acc = fcb[0];
#pragma unroll
        for (int uu = 0; uu < 64; ++uu)
            acc = fmaf(hp[uu], fcw[uu], acc);
        out[rowbase + tid] = sigm(acc);
    }
}

extern "C" void kernel_launch(void* const* d_in, const int* in_sizes, int n_in,
                              void* d_out, int out_size)
{
    const float* x   = (const float*)d_in[0];
    const float* Wih = (const float*)d_in[1];
    const float* Whh = (const float*)d_in[2];
    const float* bih = (const float*)d_in[3];
    const float* bhh = (const float*)d_in[4];
    const float* fcw = (const float*)d_in[5];
    const float* fcb = (const float*)d_in[6];
    lstm_kernel<<<296, 256>>>(x, Wih, Whh, bih, bhh, fcw, fcb, (float*)d_out);
}

// round 6
// speedup vs baseline: 1.4870x; 1.0424x over previous
#include <cuda_runtime.h>
#include <cstdint>

// LSTM: B=2048, T=1024, I=8, H=64. out = sigmoid(h_T @ fc_w^T + fc_b), [B,1] fp32.
//
// R5: each thread owns ONE output j=tid with FULL K=72 in registers (36 packed
// f32x2 weights) -> no cross-thread reduction, no partial exchange. Activation
// (tanh.approx) inline at each row-dot tail. 2 barriers/step. Grid 296 = 2
// blocks on every SM.

#define TT   1024
#define RMAX 7

typedef unsigned long long u64;

__device__ __forceinline__ u64 pk2(float lo, float hi) {
    u64 r; asm("mov.b64 %0, {%1, %2};" : "=l"(r) : "f"(lo), "f"(hi)); return r;
}
__device__ __forceinline__ void upk2(u64 v, float& lo, float& hi) {
    asm("mov.b64 {%0, %1}, %2;" : "=f"(lo), "=f"(hi) : "l"(v));
}
__device__ __forceinline__ float tanhap(float x) {
    float r; asm("tanh.approx.f32 %0, %1;" : "=f"(r) : "f"(x)); return r;
}
__device__ __forceinline__ float sigap(float x) {
    return fmaf(0.5f, tanhap(0.5f * x), 0.5f);
}

// full-K dot for row R into this thread's output, fold, activate, store gate
#define ROWACT(R) do {                                                            \
    u64 _a = biasA; uint32_t _ad = hB + (R) * 288;                                \
    u64 _h01, _h23;                                                               \
    _Pragma("unroll")                                                             \
    for (int q = 0; q < 18; ++q) {                                                \
        asm("ld.shared.v2.u64 {%0, %1}, [%2];"                                    \
            : "=l"(_h01), "=l"(_h23) : "r"(_ad + q * 16));                        \
        asm("fma.rn.f32x2 %0, %1, %2, %0;" : "+l"(_a) : "l"(w[2*q]),   "l"(_h01));\
        asm("fma.rn.f32x2 %0, %1, %2, %0;" : "+l"(_a) : "l"(w[2*q+1]), "l"(_h23));\
    }                                                                             \
    float _e, _o; upk2(_a, _e, _o);                                               \
    float _g = _e + _o;                                                           \
    float _act = istanh ? tanhap(_g) : sigap(_g);                                 \
    asm volatile("st.shared.f32 [%0], %1;"                                        \
                 :: "r"(gB + (R) * 1024 + tid * 4), "f"(_act) : "memory");        \
} while (0)

__global__ void __launch_bounds__(256, 2)
lstm_kernel(const float* __restrict__ x,     // [2048,1024,8]
            const float* __restrict__ Wih,   // [256,8]
            const float* __restrict__ Whh,   // [256,64]
            const float* __restrict__ bih,   // [256]
            const float* __restrict__ bhh,   // [256]
            const float* __restrict__ fcw,   // [64]
            const float* __restrict__ fcb,   // [1]
            float* __restrict__ out)         // [2048]
{
    __shared__ __align__(16) float s_h[RMAX][72];    // [row][k]: k<64 h, k>=64 x_t
    __shared__ __align__(16) float s_g[RMAX][256];   // activated gates

    const int tid = threadIdx.x;                     // owns output j = tid
    const int bid = blockIdx.x;
    const int nrows   = (bid < 272) ? 7 : 6;
    const int rowbase = (bid < 272) ? bid * 7 : 1904 + (bid - 272) * 6;

    // ---- persistent weights: w[q] = {W[tid][2q], W[tid][2q+1]}, K = 72 ----
    u64 w[36];
#pragma unroll
    for (int q = 0; q < 36; ++q) {
        int k = 2 * q;
        float a = (k     < 64) ? Whh[tid * 64 + k]     : Wih[tid * 8 + (k - 64)];
        float b = (k + 1 < 64) ? Whh[tid * 64 + k + 1] : Wih[tid * 8 + (k + 1 - 64)];
        w[q] = pk2(a, b);
    }
    const u64 biasA = pk2(bih[tid] + bhh[tid], 0.0f);
    const bool istanh = (tid >= 128) && (tid < 192);   // gate order i,f,g,o

    const uint32_t hB = (uint32_t)__cvta_generic_to_shared(&s_h[0][0]);
    const uint32_t gB = (uint32_t)__cvta_generic_to_shared(&s_g[0][0]);

    // ---- cell owners: thread -> (unit u, rows r0 and r0+4) ----
    const int u  = tid & 63;
    const int r0 = tid >> 6;                          // 0..3
    const bool hasR1 = (r0 < 3) && (r0 + 4 < nrows);
    float c0 = 0.0f, c1 = 0.0f;

    // ---- x stagers: threads 0..55 -> (row sr, input sxi) ----
    const int  sr  = (tid >> 3) & 7;
    const int  sxi = tid & 7;
    const bool isStager = (tid < 56) && (sr < nrows);
    const float* xrow = x + (size_t)(rowbase + sr) * (TT * 8) + sxi;

    // ---- init: zero h/x, stage x(t=0) ----
    for (int i = tid; i < RMAX * 72; i += 256)
        (&s_h[0][0])[i] = 0.0f;
    __syncthreads();
    if (isStager) s_h[sr][64 + sxi] = __ldg(xrow);
    __syncthreads();

#pragma unroll 1
    for (int t = 0; t < TT; ++t) {
        float xn = 0.0f;
        const bool pre = isStager && (t + 1 < TT);
        if (pre) xn = __ldg(xrow + (t + 1) * 8);

        // ---- phase B: full-K dots + inline activation, all 7 rows ----
        ROWACT(0); ROWACT(1); ROWACT(2); ROWACT(3);
        ROWACT(4); ROWACT(5); ROWACT(6);
        __syncthreads();

        // ---- phase E: cell/hidden update + x(t+1) staging ----
        {
            float iv = s_g[r0][u],       fv = s_g[r0][64 + u];
            float gv = s_g[r0][128 + u], ov = s_g[r0][192 + u];
            c0 = fmaf(fv, c0, iv * gv);
            s_h[r0][u] = ov * tanhap(c0);
            if (hasR1) {
                const int r1 = r0 + 4;
                float iv1 = s_g[r1][u],       fv1 = s_g[r1][64 + u];
                float gv1 = s_g[r1][128 + u], ov1 = s_g[r1][192 + u];
                c1 = fmaf(fv1, c1, iv1 * gv1);
                s_h[r1][u] = ov1 * tanhap(c1);
            }
            if (pre) s_h[sr][64 + sxi] = xn;
        }
        __syncthreads();
    }

    // ---- head: out[row] = sigmoid(h_T . fc_w + fc_b) ----
    if (tid < nrows) {
        const float* hp = s_h[tid];
        float acc = fcb[0];
#pragma unroll
        for (int uu = 0; uu < 64; ++uu)
            acc = fmaf(hp[uu], fcw[uu], acc);
        out[rowbase + tid] = sigap(acc);
    }
}

extern "C" void kernel_launch(void* const* d_in, const int* in_sizes, int n_in,
                              void* d_out, int out_size)
{
    const float* x   = (const float*)d_in[0];
    const float* Wih = (const float*)d_in[1];
    const float* Whh = (const float*)d_in[2];
    const float* bih = (const float*)d_in[3];
    const float* bhh = (const float*)d_in[4];
    const float* fcw = (const float*)d_in[5];
    const float* fcb = (const float*)d_in[6];
    lstm_kernel<<<296, 256>>>(x, Wih, Whh, bih, bhh, fcw, fcb, (float*)d_out);
}

// round 8
// speedup vs baseline: 1.6239x; 1.0920x over previous
#include <cuda_runtime.h>
#include <cstdint>

// LSTM: B=2048, T=1024, I=8, H=64. out = sigmoid(h_T @ fc_w^T + fc_b), [B,1] fp32.
//
// R6: thread owns 2 outputs (j0=2p, j1=2p+1) over HALF of K (36), with the K-half
// assigned by lane parity -> cross-K reduction is one shfl.bfly(1) pair, no smem
// round trip, still 2 barriers/step. LDS:FFMA2 issue ratio 1:4 (was 1:2).
// Weights persist in 36 packed f32x2 registers. Grid 296 = 2 blocks on every SM.

#define TT   1024
#define RMAX 7

typedef unsigned long long u64;

__device__ __forceinline__ u64 pk2(float lo, float hi) {
    u64 r; asm("mov.b64 %0, {%1, %2};" : "=l"(r) : "f"(lo), "f"(hi)); return r;
}
__device__ __forceinline__ void upk2(u64 v, float& lo, float& hi) {
    asm("mov.b64 {%0, %1}, %2;" : "=f"(lo), "=f"(hi) : "l"(v));
}
__device__ __forceinline__ float tanhap(float x) {
    float r; asm("tanh.approx.f32 %0, %1;" : "=f"(r) : "f"(x)); return r;
}
__device__ __forceinline__ float sigap(float x) {
    return fmaf(0.5f, tanhap(0.5f * x), 0.5f);
}

// Half-K dot for row R on 2 outputs, bfly-reduce across lane pair, activate, store.
#define ROWACT(R) do {                                                             \
    u64 _a0 = bias0, _a1 = bias1;                                                  \
    uint32_t _ad = hB + (R) * 288;                                                 \
    u64 _h01, _h23;                                                                \
    _Pragma("unroll")                                                              \
    for (int q = 0; q < 9; ++q) {                                                  \
        asm("ld.shared.v2.u64 {%0, %1}, [%2];"                                     \
            : "=l"(_h01), "=l"(_h23) : "r"(_ad + q * 16));                         \
        asm("fma.rn.f32x2 %0, %1, %2, %0;" : "+l"(_a0) : "l"(w0[2*q]),   "l"(_h01));\
        asm("fma.rn.f32x2 %0, %1, %2, %0;" : "+l"(_a1) : "l"(w1[2*q]),   "l"(_h01));\
        asm("fma.rn.f32x2 %0, %1, %2, %0;" : "+l"(_a0) : "l"(w0[2*q+1]), "l"(_h23));\
        asm("fma.rn.f32x2 %0, %1, %2, %0;" : "+l"(_a1) : "l"(w1[2*q+1]), "l"(_h23));\
    }                                                                              \
    float _e0, _o0, _e1, _o1;                                                      \
    upk2(_a0, _e0, _o0); upk2(_a1, _e1, _o1);                                      \
    float _s0 = _e0 + _o0, _s1 = _e1 + _o1;                                        \
    float _t0 = __shfl_xor_sync(0xffffffffu, _s0, 1);                              \
    float _t1 = __shfl_xor_sync(0xffffffffu, _s1, 1);                              \
    float _g  = kh ? (_s1 + _t1) : (_s0 + _t0);                                    \
    float _act = istanh ? tanhap(_g) : sigap(_g);                                  \
    asm volatile("st.shared.f32 [%0], %1;"                                         \
                 :: "r"(gB + (R) * 1024 + tid * 4), "f"(_act) : "memory");         \
} while (0)

__global__ void __launch_bounds__(256, 2)
lstm_kernel(const float* __restrict__ x,     // [2048,1024,8]
            const float* __restrict__ Wih,   // [256,8]
            const float* __restrict__ Whh,   // [256,64]
            const float* __restrict__ bih,   // [256]
            const float* __restrict__ bhh,   // [256]
            const float* __restrict__ fcw,   // [64]
            const float* __restrict__ fcb,   // [1]
            float* __restrict__ out)         // [2048]
{
    __shared__ __align__(16) float s_h[RMAX][72];    // [row][k]: k<64 h, k>=64 x_t
    __shared__ __align__(16) float s_g[RMAX][256];   // activated gates

    const int tid = threadIdx.x;
    const int p   = tid >> 1;       // output pair: j0 = 2p, j1 = 2p+1
    const int kh  = tid & 1;        // K-half: k in [36*kh, 36*kh+36)
    const int bid = blockIdx.x;
    const int nrows   = (bid < 272) ? 7 : 6;
    const int rowbase = (bid < 272) ? bid * 7 : 1904 + (bid - 272) * 6;

    const int j0 = 2 * p;
    const int kb = kh * 36;

    // ---- persistent weights: w0 for output j0, w1 for j0+1, this K-half ----
    u64 w0[18], w1[18];
#pragma unroll
    for (int q = 0; q < 18; ++q) {
        int k = kb + 2 * q;
        float a = (k     < 64) ? Whh[j0 * 64 + k]           : Wih[j0 * 8 + (k - 64)];
        float b = (k + 1 < 64) ? Whh[j0 * 64 + k + 1]       : Wih[j0 * 8 + (k + 1 - 64)];
        float c = (k     < 64) ? Whh[(j0 + 1) * 64 + k]     : Wih[(j0 + 1) * 8 + (k - 64)];
        float d = (k + 1 < 64) ? Whh[(j0 + 1) * 64 + k + 1] : Wih[(j0 + 1) * 8 + (k + 1 - 64)];
        w0[q] = pk2(a, b);
        w1[q] = pk2(c, d);
    }
    u64 bias0 = 0ULL, bias1 = 0ULL;
    if (kh == 0) {   // bias injected once per output (even lane only)
        bias0 = pk2(bih[j0] + bhh[j0], 0.0f);
        bias1 = pk2(bih[j0 + 1] + bhh[j0 + 1], 0.0f);
    }
    const bool istanh = (p >= 64) && (p < 96);   // outputs 128..191 = g gate (tanh)

    const uint32_t hB = (uint32_t)__cvta_generic_to_shared(&s_h[0][0]) + kb * 4;
    const uint32_t gB = (uint32_t)__cvta_generic_to_shared(&s_g[0][0]);

    // ---- cell owners: thread -> (unit u, rows r0 and r0+4) ----
    const int u  = tid & 63;
    const int r0 = tid >> 6;                          // 0..3
    const bool hasR1 = (r0 < 3) && (r0 + 4 < nrows);
    float c0 = 0.0f, c1 = 0.0f;

    // ---- x stagers: threads 0..55 -> (row sr, input sxi) ----
    const int  sr  = (tid >> 3) & 7;
    const int  sxi = tid & 7;
    const bool isStager = (tid < 56) && (sr < nrows);
    const float* xrow = x + (size_t)(rowbase + sr) * (TT * 8) + sxi;

    // ---- init: zero h/x, stage x(t=0) ----
    for (int i = tid; i < RMAX * 72; i += 256)
        (&s_h[0][0])[i] = 0.0f;
    __syncthreads();
    if (isStager) s_h[sr][64 + sxi] = __ldg(xrow);
    __syncthreads();

#pragma unroll 1
    for (int t = 0; t < TT; ++t) {
        float xn = 0.0f;
        const bool pre = isStager && (t + 1 < TT);
        if (pre) xn = __ldg(xrow + (t + 1) * 8);

        // ---- phase B: half-K dots, bfly reduce, inline activation, all rows ----
        ROWACT(0); ROWACT(1); ROWACT(2); ROWACT(3);
        ROWACT(4); ROWACT(5); ROWACT(6);
        __syncthreads();

        // ---- phase E: cell/hidden update + x(t+1) staging ----
        {
            float iv = s_g[r0][u],       fv = s_g[r0][64 + u];
            float gv = s_g[r0][128 + u], ov = s_g[r0][192 + u];
            c0 = fmaf(fv, c0, iv * gv);
            s_h[r0][u] = ov * tanhap(c0);
            if (hasR1) {
                const int r1 = r0 + 4;
                float iv1 = s_g[r1][u],       fv1 = s_g[r1][64 + u];
                float gv1 = s_g[r1][128 + u], ov1 = s_g[r1][192 + u];
                c1 = fmaf(fv1, c1, iv1 * gv1);
                s_h[r1][u] = ov1 * tanhap(c1);
            }
            if (pre) s_h[sr][64 + sxi] = xn;
        }
        __syncthreads();
    }

    // ---- head: out[row] = sigmoid(h_T . fc_w + fc_b) ----
    if (tid < nrows) {
        const float* hp = s_h[tid];
        float acc = fcb[0];
#pragma unroll
        for (int uu = 0; uu < 64; ++uu)
            acc = fmaf(hp[uu], fcw[uu], acc);
        out[rowbase + tid] = sigap(acc);
    }
}

extern "C" void kernel_launch(void* const* d_in, const int* in_sizes, int n_in,
                              void* d_out, int out_size)
{
    const float* x   = (const float*)d_in[0];
    const float* Wih = (const float*)d_in[1];
    const float* Whh = (const float*)d_in[2];
    const float* bih = (const float*)d_in[3];
    const float* bhh = (const float*)d_in[4];
    const float* fcw = (const float*)d_in[5];
    const float* fcb = (const float*)d_in[6];
    lstm_kernel<<<296, 256>>>(x, Wih, Whh, bih, bhh, fcw, fcb, (float*)d_out);
}

// round 9
// speedup vs baseline: 1.6907x; 1.0411x over previous
#include <cuda_runtime.h>
#include <cstdint>

// LSTM: B=2048, T=1024, I=8, H=64. out = sigmoid(h_T @ fc_w^T + fc_b), [B,1] fp32.
//
// R7: quad-gate layout. Thread tid -> unit u = tid>>2; lane-in-quad encodes
// (gate-pair, K-half): {(i,f)|(g,o)} x {K[0:36)|K[36:72)}. Each thread: 2 outputs
// x half-K in 36 packed f32x2 registers. Per row: 9 LDS.128 + 36 FFMA2 + fold +
// shfl.xor(1) + shfl.xor(2) -> every quad lane holds all 4 gate sums; owner lane
// keeps them. After all rows: full-width activation + c/h update, h written to
// ping-pong buffer. ONE __syncthreads per timestep. Grid 296 = 2 blocks/SM.

#define TT   1024
#define RMAX 7

typedef unsigned long long u64;

__device__ __forceinline__ u64 pk2(float lo, float hi) {
    u64 r; asm("mov.b64 %0, {%1, %2};" : "=l"(r) : "f"(lo), "f"(hi)); return r;
}
__device__ __forceinline__ void upk2(u64 v, float& lo, float& hi) {
    asm("mov.b64 {%0, %1}, %2;" : "=f"(lo), "=f"(hi) : "l"(v));
}
__device__ __forceinline__ float tanhap(float x) {
    float r; asm("tanh.approx.f32 %0, %1;" : "=f"(r) : "f"(x)); return r;
}
__device__ __forceinline__ float sigap(float x) {
    return fmaf(0.5f, tanhap(0.5f * x), 0.5f);
}

// Row R: half-K dot on 2 outputs, fold, quad reduce/exchange, stash gates if owner.
#define ROWG(R, RD) do {                                                            \
    u64 _a0 = bias0, _a1 = bias1;                                                   \
    uint32_t _ad = (RD) + (R) * 288 + khoff;                                        \
    u64 _h01, _h23;                                                                 \
    _Pragma("unroll")                                                               \
    for (int q = 0; q < 9; ++q) {                                                   \
        asm("ld.shared.v2.u64 {%0, %1}, [%2];"                                      \
            : "=l"(_h01), "=l"(_h23) : "r"(_ad + q * 16));                          \
        asm("fma.rn.f32x2 %0, %1, %2, %0;" : "+l"(_a0) : "l"(w0[2*q]),   "l"(_h01));\
        asm("fma.rn.f32x2 %0, %1, %2, %0;" : "+l"(_a1) : "l"(w1[2*q]),   "l"(_h01));\
        asm("fma.rn.f32x2 %0, %1, %2, %0;" : "+l"(_a0) : "l"(w0[2*q+1]), "l"(_h23));\
        asm("fma.rn.f32x2 %0, %1, %2, %0;" : "+l"(_a1) : "l"(w1[2*q+1]), "l"(_h23));\
    }                                                                               \
    float _e0, _o0, _e1, _o1;                                                       \
    upk2(_a0, _e0, _o0); upk2(_a1, _e1, _o1);                                       \
    float _s0 = _e0 + _o0, _s1 = _e1 + _o1;                                         \
    _s0 += __shfl_xor_sync(0xffffffffu, _s0, 1);   /* combine K-halves */           \
    _s1 += __shfl_xor_sync(0xffffffffu, _s1, 1);                                    \
    float _r0 = __shfl_xor_sync(0xffffffffu, _s0, 2);  /* swap gate pairs */        \
    float _r1 = __shfl_xor_sync(0xffffffffu, _s1, 2);                               \
    float _gi = gsel ? _r0 : _s0;                                                   \
    float _gf = gsel ? _r1 : _s1;                                                   \
    float _gg = gsel ? _s0 : _r0;                                                   \
    float _go = gsel ? _s1 : _r1;                                                   \
    if ((R) < 4) { if (lq == (R))     { iA=_gi; fA=_gf; gA=_gg; oA=_go; } }         \
    else         { if (lq == (R) - 4) { iB=_gi; fB=_gf; gB=_gg; oB=_go; } }         \
} while (0)

__global__ void __launch_bounds__(256, 2)
lstm_kernel(const float* __restrict__ x,     // [2048,1024,8]
            const float* __restrict__ Wih,   // [256,8]
            const float* __restrict__ Whh,   // [256,64]
            const float* __restrict__ bih,   // [256]
            const float* __restrict__ bhh,   // [256]
            const float* __restrict__ fcw,   // [64]
            const float* __restrict__ fcb,   // [1]
            float* __restrict__ out)         // [2048]
{
    __shared__ __align__(16) float s_h[2][RMAX][72];  // ping-pong: [buf][row][k]

    const int tid  = threadIdx.x;
    const int u    = tid >> 2;      // unit 0..63 (quad fully inside a warp)
    const int lq   = tid & 3;       // lane-in-quad
    const int kh   = lq & 1;        // K-half
    const int gsel = lq >> 1;       // 0: (i,f) outputs, 1: (g,o) outputs
    const int bid  = blockIdx.x;
    const int nrows   = (bid < 272) ? 7 : 6;
    const int rowbase = (bid < 272) ? bid * 7 : 1904 + (bid - 272) * 6;
    const bool seven  = (nrows == 7);

    const int jA = gsel * 128 + u;        // i (or g) row of the weight matrix
    const int jB = gsel * 128 + 64 + u;   // f (or o)
    const int kb = kh * 36;
    const uint32_t khoff = (uint32_t)(kb * 4);

    // ---- persistent weights: this K-half of outputs jA, jB ----
    u64 w0[18], w1[18];
#pragma unroll
    for (int q = 0; q < 18; ++q) {
        int k = kb + 2 * q;
        float a = (k     < 64) ? Whh[jA * 64 + k]     : Wih[jA * 8 + (k - 64)];
        float b = (k + 1 < 64) ? Whh[jA * 64 + k + 1] : Wih[jA * 8 + (k + 1 - 64)];
        float c = (k     < 64) ? Whh[jB * 64 + k]     : Wih[jB * 8 + (k - 64)];
        float d = (k + 1 < 64) ? Whh[jB * 64 + k + 1] : Wih[jB * 8 + (k + 1 - 64)];
        w0[q] = pk2(a, b);
        w1[q] = pk2(c, d);
    }
    u64 bias0 = 0ULL, bias1 = 0ULL;
    if (kh == 0) {   // bias counted exactly once per output
        bias0 = pk2(bih[jA] + bhh[jA], 0.0f);
        bias1 = pk2(bih[jB] + bhh[jB], 0.0f);
    }

    // ---- owned rows: rowA = lq (always exists), rowB = lq+4 (maybe) ----
    const int rowA = lq, rowB = lq + 4;
    const bool hasB = (rowB < nrows);
    float cA = 0.0f, cB = 0.0f;
    float iA = 0, fA = 0, gA = 0, oA = 0, iB = 0, fB = 0, gB = 0, oB = 0;

    // ---- x stagers: threads 0..55 -> (row sr, input sxi) ----
    const int  sr  = (tid >> 3) & 7;
    const int  sxi = tid & 7;
    const bool isStager = (tid < 56) && (sr < nrows);
    const float* xrow = x + (size_t)(rowbase + sr) * (TT * 8) + sxi;

    uint32_t hB0 = (uint32_t)__cvta_generic_to_shared(&s_h[0][0][0]);
    uint32_t hB1 = (uint32_t)__cvta_generic_to_shared(&s_h[1][0][0]);

    // ---- init buf0: h = 0, x(0) staged ----
    for (int i = tid; i < RMAX * 72; i += 256)
        (&s_h[0][0][0])[i] = 0.0f;
    __syncthreads();
    if (isStager) s_h[0][sr][64 + sxi] = __ldg(xrow);
    __syncthreads();

    uint32_t rd = hB0, wr = hB1;

#pragma unroll 1
    for (int t = 0; t < TT; ++t) {
        float xn = 0.0f;
        const bool pre = isStager && (t + 1 < TT);
        if (pre) xn = __ldg(xrow + (t + 1) * 8);

        // ---- row dots + in-warp gate gather ----
        ROWG(0, rd); ROWG(1, rd); ROWG(2, rd);
        ROWG(3, rd); ROWG(4, rd); ROWG(5, rd);
        if (seven) ROWG(6, rd);

        // ---- full-width activation + state update, write h(t+1) to wr ----
        {
            cA = fmaf(sigap(fA), cA, sigap(iA) * tanhap(gA));
            float hA = sigap(oA) * tanhap(cA);
            asm volatile("st.shared.f32 [%0], %1;"
                         :: "r"(wr + rowA * 288 + u * 4), "f"(hA) : "memory");
            if (hasB) {
                cB = fmaf(sigap(fB), cB, sigap(iB) * tanhap(gB));
                float hBv = sigap(oB) * tanhap(cB);
                asm volatile("st.shared.f32 [%0], %1;"
                             :: "r"(wr + rowB * 288 + u * 4), "f"(hBv) : "memory");
            }
            if (pre) {
                asm volatile("st.shared.f32 [%0], %1;"
                             :: "r"(wr + sr * 288 + (64 + sxi) * 4), "f"(xn) : "memory");
            }
        }
        __syncthreads();

        uint32_t tmp = rd; rd = wr; wr = tmp;
    }

    // TT even -> final h lives in buf0
    if (tid < nrows) {
        const float* hp = s_h[0][tid];
        float acc = fcb[0];
#pragma unroll
        for (int uu = 0; uu < 64; ++uu)
            acc = fmaf(hp[uu], fcw[uu], acc);
        out[rowbase + tid] = sigap(acc);
    }
}

extern "C" void kernel_launch(void* const* d_in, const int* in_sizes, int n_in,
                              void* d_out, int out_size)
{
    const float* x   = (const float*)d_in[0];
    const float* Wih = (const float*)d_in[1];
    const float* Whh = (const float*)d_in[2];
    const float* bih = (const float*)d_in[3];
    const float* bhh = (const float*)d_in[4];
    const float* fcw = (const float*)d_in[5];
    const float* fcb = (const float*)d_in[6];
    lstm_kernel<<<296, 256>>>(x, Wih, Whh, bih, bhh, fcw, fcb, (float*)d_out);
}

// round 10
// speedup vs baseline: 1.7180x; 1.0162x over previous
#include <cuda_runtime.h>
#include <cstdint>

// LSTM: B=2048, T=1024, I=8, H=64. out = sigmoid(h_T @ fc_w^T + fc_b), [B,1] fp32.
//
// R9: quad-gate layout (unit u = tid>>2; lane-in-quad = (gate-pair, K-half)).
// Per row: 9 LDS.128 + 36 FFMA2 + fold + shfl.xor(1) + shfl.xor(2); stash RAW
// quad values (no gate-select SELs in the hot path). State update split:
// rows 0-3 updated between ROWG(3) and ROWG(4) so the MUFU chain hides under
// rows 4-6's FMA stream. ONE __syncthreads per timestep, ping-pong h buffer.
// Grid 296 = 2 blocks on every SM.

#define TT   1024
#define RMAX 7

typedef unsigned long long u64;

__device__ __forceinline__ u64 pk2(float lo, float hi) {
    u64 r; asm("mov.b64 %0, {%1, %2};" : "=l"(r) : "f"(lo), "f"(hi)); return r;
}
__device__ __forceinline__ void upk2(u64 v, float& lo, float& hi) {
    asm("mov.b64 {%0, %1}, %2;" : "=f"(lo), "=f"(hi) : "l"(v));
}
__device__ __forceinline__ float tanhap(float x) {
    float r; asm("tanh.approx.f32 %0, %1;" : "=f"(r) : "f"(x)); return r;
}
__device__ __forceinline__ float sigap(float x) {
    return fmaf(0.5f, tanhap(0.5f * x), 0.5f);
}

// Row R: half-K dot on 2 outputs, fold, quad all-gather; stash 4 RAW values
// (s0 s1 = this lane's outputs, r0 r1 = partner pair's) for the owner lane.
#define ROWG(R, RD) do {                                                            \
    u64 _a0 = bias0, _a1 = bias1;                                                   \
    uint32_t _ad = (RD) + (R) * 288 + khoff;                                        \
    u64 _h01, _h23;                                                                 \
    _Pragma("unroll")                                                               \
    for (int q = 0; q < 9; ++q) {                                                   \
        asm("ld.shared.v2.u64 {%0, %1}, [%2];"                                      \
            : "=l"(_h01), "=l"(_h23) : "r"(_ad + q * 16));                          \
        asm("fma.rn.f32x2 %0, %1, %2, %0;" : "+l"(_a0) : "l"(w0[2*q]),   "l"(_h01));\
        asm("fma.rn.f32x2 %0, %1, %2, %0;" : "+l"(_a1) : "l"(w1[2*q]),   "l"(_h01));\
        asm("fma.rn.f32x2 %0, %1, %2, %0;" : "+l"(_a0) : "l"(w0[2*q+1]), "l"(_h23));\
        asm("fma.rn.f32x2 %0, %1, %2, %0;" : "+l"(_a1) : "l"(w1[2*q+1]), "l"(_h23));\
    }                                                                               \
    float _e0, _o0, _e1, _o1;                                                       \
    upk2(_a0, _e0, _o0); upk2(_a1, _e1, _o1);                                       \
    float _s0 = _e0 + _o0, _s1 = _e1 + _o1;                                         \
    _s0 += __shfl_xor_sync(0xffffffffu, _s0, 1);   /* combine K-halves */           \
    _s1 += __shfl_xor_sync(0xffffffffu, _s1, 1);                                    \
    float _r0 = __shfl_xor_sync(0xffffffffu, _s0, 2);  /* partner gate pair */      \
    float _r1 = __shfl_xor_sync(0xffffffffu, _s1, 2);                               \
    if ((R) < 4) { if (lq == (R))     { sA0=_s0; sA1=_s1; rA0=_r0; rA1=_r1; } }     \
    else         { if (lq == (R) - 4) { sB0=_s0; sB1=_s1; rB0=_r0; rB1=_r1; } }     \
} while (0)

__global__ void __launch_bounds__(256, 2)
lstm_kernel(const float* __restrict__ x,     // [2048,1024,8]
            const float* __restrict__ Wih,   // [256,8]
            const float* __restrict__ Whh,   // [256,64]
            const float* __restrict__ bih,   // [256]
            const float* __restrict__ bhh,   // [256]
            const float* __restrict__ fcw,   // [64]
            const float* __restrict__ fcb,   // [1]
            float* __restrict__ out)         // [2048]
{
    __shared__ __align__(16) float s_h[2][RMAX][72];  // ping-pong: [buf][row][k]

    const int tid  = threadIdx.x;
    const int u    = tid >> 2;      // unit 0..63
    const int lq   = tid & 3;       // lane-in-quad
    const int kh   = lq & 1;        // K-half
    const int gsel = lq >> 1;       // 0: owns (i,f); 1: owns (g,o)
    const int bid  = blockIdx.x;
    const int nrows   = (bid < 272) ? 7 : 6;
    const int rowbase = (bid < 272) ? bid * 7 : 1904 + (bid - 272) * 6;
    const bool seven  = (nrows == 7);

    const int jA = gsel * 128 + u;        // i (or g)
    const int jB = gsel * 128 + 64 + u;   // f (or o)
    const int kb = kh * 36;
    const uint32_t khoff = (uint32_t)(kb * 4);

    // ---- persistent weights: this K-half of outputs jA, jB ----
    u64 w0[18], w1[18];
#pragma unroll
    for (int q = 0; q < 18; ++q) {
        int k = kb + 2 * q;
        float a = (k     < 64) ? Whh[jA * 64 + k]     : Wih[jA * 8 + (k - 64)];
        float b = (k + 1 < 64) ? Whh[jA * 64 + k + 1] : Wih[jA * 8 + (k + 1 - 64)];
        float c = (k     < 64) ? Whh[jB * 64 + k]     : Wih[jB * 8 + (k - 64)];
        float d = (k + 1 < 64) ? Whh[jB * 64 + k + 1] : Wih[jB * 8 + (k + 1 - 64)];
        w0[q] = pk2(a, b);
        w1[q] = pk2(c, d);
    }
    u64 bias0 = 0ULL, bias1 = 0ULL;
    if (kh == 0) {
        bias0 = pk2(bih[jA] + bhh[jA], 0.0f);
        bias1 = pk2(bih[jB] + bhh[jB], 0.0f);
    }

    // ---- owned rows: rowA = lq, rowB = lq+4 ----
    const int rowA = lq, rowB = lq + 4;
    const bool hasB = (rowB < nrows);
    float cA = 0.0f, cB = 0.0f;
    float sA0 = 0, sA1 = 0, rA0 = 0, rA1 = 0;
    float sB0 = 0, sB1 = 0, rB0 = 0, rB1 = 0;

    // ---- x stagers: threads 0..55 -> (row sr, input sxi) ----
    const int  sr  = (tid >> 3) & 7;
    const int  sxi = tid & 7;
    const bool isStager = (tid < 56) && (sr < nrows);
    const float* xrow = x + (size_t)(rowbase + sr) * (TT * 8) + sxi;

    uint32_t hB0 = (uint32_t)__cvta_generic_to_shared(&s_h[0][0][0]);
    uint32_t hB1 = (uint32_t)__cvta_generic_to_shared(&s_h[1][0][0]);

    // ---- init buf0: h = 0, x(0) staged ----
    for (int i = tid; i < RMAX * 72; i += 256)
        (&s_h[0][0][0])[i] = 0.0f;
    __syncthreads();
    if (isStager) s_h[0][sr][64 + sxi] = __ldg(xrow);
    __syncthreads();

    uint32_t rd = hB0, wr = hB1;

#pragma unroll 1
    for (int t = 0; t < TT; ++t) {
        float xn = 0.0f;
        const bool pre = isStager && (t + 1 < TT);
        if (pre) xn = __ldg(xrow + (t + 1) * 8);

        // ---- rows 0-3: dots + gather ----
        ROWG(0, rd); ROWG(1, rd); ROWG(2, rd); ROWG(3, rd);

        // ---- updateA (rowA gates complete) — hidden under rows 4-6 FMA ----
        {
            float gi = gsel ? rA0 : sA0;
            float gf = gsel ? rA1 : sA1;
            float gg = gsel ? sA0 : rA0;
            float go = gsel ? sA1 : rA1;
            cA = fmaf(sigap(gf), cA, sigap(gi) * tanhap(gg));
            float hA = sigap(go) * tanhap(cA);
            asm volatile("st.shared.f32 [%0], %1;"
                         :: "r"(wr + rowA * 288 + u * 4), "f"(hA) : "memory");
            if (pre) {
                asm volatile("st.shared.f32 [%0], %1;"
                             :: "r"(wr + sr * 288 + (64 + sxi) * 4), "f"(xn) : "memory");
            }
        }

        // ---- rows 4-6: dots + gather ----
        ROWG(4, rd); ROWG(5, rd);
        if (seven) ROWG(6, rd);

        // ---- updateB ----
        if (hasB) {
            float gi = gsel ? rB0 : sB0;
            float gf = gsel ? rB1 : sB1;
            float gg = gsel ? sB0 : rB0;
            float go = gsel ? sB1 : rB1;
            cB = fmaf(sigap(gf), cB, sigap(gi) * tanhap(gg));
            float hBv = sigap(go) * tanhap(cB);
            asm volatile("st.shared.f32 [%0], %1;"
                         :: "r"(wr + rowB * 288 + u * 4), "f"(hBv) : "memory");
        }
        __syncthreads();

        uint32_t tmp = rd; rd = wr; wr = tmp;
    }

    // TT even -> final h lives in buf0
    if (tid < nrows) {
        const float* hp = s_h[0][tid];
        float acc = fcb[0];
#pragma unroll
        for (int uu = 0; uu < 64; ++uu)
            acc = fmaf(hp[uu], fcw[uu], acc);
        out[rowbase + tid] = sigap(acc);
    }
}

extern "C" void kernel_launch(void* const* d_in, const int* in_sizes, int n_in,
                              void* d_out, int out_size)
{
    const float* x   = (const float*)d_in[0];
    const float* Wih = (const float*)d_in[1];
    const float* Whh = (const float*)d_in[2];
    const float* bih = (const float*)d_in[3];
    const float* bhh = (const float*)d_in[4];
    const float* fcw = (const float*)d_in[5];
    const float* fcb = (const float*)d_in[6];
    lstm_kernel<<<296, 256>>>(x, Wih, Whh, bih, bhh, fcw, fcb, (float*)d_out);
}